// round 15
// baseline (speedup 1.0000x reference)
#include <cuda_runtime.h>
#include <cuda.h>
#include <cuda_fp16.h>
#include <cstdint>

// ============================================================================
// TernaryLinear: out[8192,4096] = x[8192,4096] @ (ternary(w)[4096,4096]).T
//
// out = (x @ q^T) * scale[col], q in {-1,0,1} exact in fp16; x -> fp16
// (u=2^-11 => ~3.5e-4 rel err, measured). fp32 accumulate in registers.
//
// R15 = R13 (best passing: 542.8us, tensor 91.1%) + 3-way wait stagger ONLY.
// R14's failure isolated to the EMPTY-arrive hoist (arrive abutting the
// last LDSM races TMA overwrite -> LDSM/ATOMS are not mutually ordered);
// the wait stagger itself is correctness-neutral (an earlier FULL wait only
// blocks longer). So: FULL(i+1) wait at ks==wpos=(bid>>2)%3 in {0,1,2} --
// no CTA waits at ks=3 on the critical path -- while the EMPTY arrive
// stays at END of iteration (proven placement, count-128 per-thread).
// Geometry: 3 CTAs/SM x 128 thr, 128x64 tiles, 64x32 warp tiles, BK=64,
// 3-stage TMA pipeline, rotating duty warp, cross-chunk ldmatrix prefetch,
// register frag double-buffering.
// ============================================================================

#define DINLINE __device__ __forceinline__

static constexpr int M = 8192, N = 4096, K = 4096;
static constexpr int BM = 128, BN = 64, BK = 64;
static constexpr int CHUNKS = K / BK;                  // 64
static constexpr int STAGES = 3;
static constexpr int STAGE_BYTES = (BM + BN) * BK * 2; // 24576
static constexpr int SMEM_STAGE0 = 1024;               // barriers live below
static constexpr int SMEM_SIZE = SMEM_STAGE0 + STAGES * STAGE_BYTES; // 74752

// scratch (device globals: allocation-free)
__device__ __half g_q[(size_t)N * K];     // ternary weights, fp16 exact
__device__ __half g_xh[(size_t)M * K];    // x in fp16
__device__ float  g_scale[N];

// ---------------------------------------------------------------------------
// helpers
// ---------------------------------------------------------------------------
DINLINE uint32_t smem_u32(const void* p) {
    uint32_t a;
    asm("{ .reg .u64 t; cvta.to.shared.u64 t, %1; cvt.u32.u64 %0, t; }" : "=r"(a) : "l"(p));
    return a;
}
DINLINE uint32_t elect_one() {
    uint32_t p;
    asm volatile("{ .reg .pred p; elect.sync _|p, 0xFFFFFFFF; selp.b32 %0, 1, 0, p; }" : "=r"(p));
    return p;
}
#define MBAR_INIT(a, c) asm volatile("mbarrier.init.shared.b64 [%0], %1;" :: "r"(a), "r"(c) : "memory")
#define MBAR_ARRIVE(a)  asm volatile("mbarrier.arrive.shared.b64 _, [%0];" :: "r"(a) : "memory")
#define MBAR_EXPECT_TX(a, b) asm volatile("mbarrier.arrive.expect_tx.shared.b64 _, [%0], %1;" :: "r"(a), "r"(b) : "memory")
#define MBAR_WAIT(a, ph) do {                                                     \
    uint32_t _m = (a), _p = (ph), _d;                                             \
    asm volatile("{ .reg .pred p; mbarrier.try_wait.parity.acquire.cta.shared::cta.b64 p, [%1], %2; selp.b32 %0,1,0,p; }" \
        : "=r"(_d) : "r"(_m), "r"(_p) : "memory");                                \
    if (!_d) {                                                                    \
        asm volatile("{ .reg .pred P1; W%=: mbarrier.try_wait.parity.acquire.cta.shared::cta.b64 P1, [%0], %1, 0x989680; @P1 bra.uni D%=; bra.uni W%=; D%=: }" \
            :: "r"(_m), "r"(_p) : "memory");                                      \
    }                                                                             \
} while (0)

#define TMA_LOAD_2D(smem, map, cx, cy, mbar)                                      \
    asm volatile("cp.async.bulk.tensor.2d.shared::cta.global.tile.mbarrier::complete_tx::bytes [%0], [%1, {%2, %3}], [%4];" \
        :: "r"(smem), "l"(map), "r"(cx), "r"(cy), "r"(mbar) : "memory")

DINLINE void ldsm4(uint32_t* r, uint32_t addr) {
    asm volatile("ldmatrix.sync.aligned.m8n8.x4.shared.b16 {%0,%1,%2,%3}, [%4];"
                 : "=r"(r[0]), "=r"(r[1]), "=r"(r[2]), "=r"(r[3]) : "r"(addr));
}
DINLINE void mma16816(float* c, const uint32_t* a, const uint32_t* b) {
    asm volatile(
        "mma.sync.aligned.m16n8k16.row.col.f32.f16.f16.f32 "
        "{%0,%1,%2,%3}, {%4,%5,%6,%7}, {%8,%9}, {%0,%1,%2,%3};"
        : "+f"(c[0]), "+f"(c[1]), "+f"(c[2]), "+f"(c[3])
        : "r"(a[0]), "r"(a[1]), "r"(a[2]), "r"(a[3]), "r"(b[0]), "r"(b[1]));
}

// ---------------------------------------------------------------------------
// Fused prep: blocks [0, N) quantize w rows (one-pass, row in registers);
// blocks [N, N + M*K/2048) convert x to fp16.
// ---------------------------------------------------------------------------
__global__ void __launch_bounds__(256) prep_kernel(const float* __restrict__ w,
                                                   const float* __restrict__ x) {
    if (blockIdx.x < (unsigned)N) {
        const int row = blockIdx.x, tid = threadIdx.x;
        const float4* wr = reinterpret_cast<const float4*>(w + (size_t)row * K);
        float4 v[4];
        float s = 0.f;
        #pragma unroll
        for (int t = 0; t < 4; t++) {
            v[t] = wr[tid + 256 * t];
            s += fabsf(v[t].x) + fabsf(v[t].y) + fabsf(v[t].z) + fabsf(v[t].w);
        }
        for (int o = 16; o; o >>= 1) s += __shfl_xor_sync(~0u, s, o);
        __shared__ float warp_s[8];
        __shared__ float sc;
        if ((tid & 31) == 0) warp_s[tid >> 5] = s;
        __syncthreads();
        if (tid == 0) {
            float t = 0.f;
            for (int i = 0; i < 8; i++) t += warp_s[i];
            float m = t * (1.f / (float)K);
            if (m < 1e-5f) m = 1e-5f;
            sc = m;
            g_scale[row] = m;
        }
        __syncthreads();
        const float inv = 1.f / sc;
        __half2* qr = reinterpret_cast<__half2*>(g_q + (size_t)row * K);
        #pragma unroll
        for (int t = 0; t < 4; t++) {
            float q0 = fminf(fmaxf(rintf(v[t].x * inv), -1.f), 1.f);
            float q1 = fminf(fmaxf(rintf(v[t].y * inv), -1.f), 1.f);
            float q2 = fminf(fmaxf(rintf(v[t].z * inv), -1.f), 1.f);
            float q3 = fminf(fmaxf(rintf(v[t].w * inv), -1.f), 1.f);
            qr[2 * (tid + 256 * t)]     = __floats2half2_rn(q0, q1);
            qr[2 * (tid + 256 * t) + 1] = __floats2half2_rn(q2, q3);
        }
    } else {
        size_t i = (size_t)(blockIdx.x - N) * 256 + threadIdx.x;  // 8 floats each
        const float4* x4 = reinterpret_cast<const float4*>(x);
        float4 a = x4[2 * i], b = x4[2 * i + 1];
        __half2 h0 = __floats2half2_rn(a.x, a.y);
        __half2 h1 = __floats2half2_rn(a.z, a.w);
        __half2 h2 = __floats2half2_rn(b.x, b.y);
        __half2 h3 = __floats2half2_rn(b.z, b.w);
        uint4 o;
        o.x = *reinterpret_cast<uint32_t*>(&h0);
        o.y = *reinterpret_cast<uint32_t*>(&h1);
        o.z = *reinterpret_cast<uint32_t*>(&h2);
        o.w = *reinterpret_cast<uint32_t*>(&h3);
        reinterpret_cast<uint4*>(g_xh)[i] = o;
    }
}

// ---------------------------------------------------------------------------
// GEMM: CTA 128x64, BK=64, 3-stage TMA+mbarrier pipeline, 4 warps (2m x 2n),
// 3 CTAs/SM (3 warps per SMSP). Warp tile 64x32 via mma.sync.m16n8k16,
// register frag double-buffering with cross-chunk prefetch.
// FULL waits 3-way staggered at ks in {0,1,2}; EMPTY count-128 per-thread
// arrives at END of iteration (proven-safe placement from R13).
// ---------------------------------------------------------------------------
__global__ void __launch_bounds__(128, 3) gemm_kernel(
    const __grid_constant__ CUtensorMap tmA,
    const __grid_constant__ CUtensorMap tmB,
    float* __restrict__ out)        // [M,N] fp32
{
    extern __shared__ char smem[];
    const uint32_t sbase = smem_u32(smem);
    const int tid = threadIdx.x, lane = tid & 31, wid = tid >> 5;
    const int wm = wid >> 1, wn = wid & 1;     // warp tile: (wm*64, wn*32)
    const int mrow = blockIdx.y * BM;
    const int nbase = blockIdx.x * BN;
    const unsigned bid = blockIdx.y * gridDim.x + blockIdx.x;
    const int wpos = (int)((bid >> 2) % 3u);   // 3-way wait stagger: ks position

    // barriers: full[0..2] at sbase+0,16,32 ; empty[0..2] at sbase+48,64,80
    const uint32_t FULL = sbase, EMPTY = sbase + 48;
    const uint32_t STAGE0 = sbase + SMEM_STAGE0;

    if (tid == 0) {
        #pragma unroll
        for (int s = 0; s < 3; s++) {
            MBAR_INIT(FULL + 16 * s, 1);
            MBAR_INIT(EMPTY + 16 * s, 128);    // per-thread arrives
        }
    }
    __syncthreads();

    float acc[4][4][4];
    #pragma unroll
    for (int i = 0; i < 4; i++)
        #pragma unroll
        for (int j = 0; j < 4; j++)
            #pragma unroll
            for (int k = 0; k < 4; k++) acc[i][j][k] = 0.f;

    // ldmatrix lane coords
    const int arow = lane & 15, asel = lane >> 4;
    const int brow = (lane & 7) + ((lane >> 4) << 3), bsel = (lane >> 3) & 1;
    const int axor = arow & 7, bxor = brow & 7;

    // TMA stage issue (caller must be warp-uniform; elected lane only)
    auto issue_stage = [&](int s, int kc) {
        const uint32_t sA = STAGE0 + s * STAGE_BYTES;
        MBAR_EXPECT_TX(FULL + 16 * s, (uint32_t)STAGE_BYTES);
        TMA_LOAD_2D(sA,            &tmA, kc * BK, mrow,  FULL + 16 * s);
        TMA_LOAD_2D(sA + BM * 128, &tmB, kc * BK, nbase, FULL + 16 * s);
    };

    uint32_t af[2][4][4], bf[2][2][4];

    auto load_frags = [&](int s, int ks, int buf) {
        const uint32_t aB = STAGE0 + s * STAGE_BYTES;
        const uint32_t bB = aB + BM * 128;
        #pragma unroll
        for (int mt = 0; mt < 4; mt++) {
            const int row = wm * 64 + mt * 16 + arow;
            ldsm4(af[buf][mt], aB + row * 128 + (((ks * 2 + asel) ^ axor) << 4));
        }
        #pragma unroll
        for (int p = 0; p < 2; p++) {
            const int row = wn * 32 + p * 16 + brow;
            ldsm4(bf[buf][p], bB + row * 128 + (((ks * 2 + bsel) ^ bxor) << 4));
        }
    };

    // prologue: issue chunks 0 and 1; wait chunk 0; prefetch frags(0,0)
    if (wid == 0 && elect_one()) {
        issue_stage(0, 0);
        issue_stage(1, 1);
    }
    MBAR_WAIT(FULL + 0, 0);
    load_frags(0, 0, 0);

    for (int i = 0; i < CHUNKS; i++) {
        const int scur = i % STAGES;
        const int s1 = (i + 1) % STAGES;
        const uint32_t ph1 = ((i + 1) / 3) & 1;

        #pragma unroll
        for (int ks = 0; ks < 4; ks++) {
            const int b = ks & 1;
            // 3-way staggered FULL(i+1) wait at ks==wpos (0,1,2): chunk i+1
            // was issued during iteration i-1 -> near-always fast path;
            // never sits immediately before the dependent frag load.
            if (ks == wpos && i + 1 < CHUNKS) {
                MBAR_WAIT(FULL + 16 * s1, ph1);
            }
            if (ks == 1 && i + 2 < CHUNKS && wid == ((i + 2) & 3)) {
                // rotate TMA-issue duty across warps; WAR-gate on empty
                if (elect_one()) {
                    const int s2 = (i + 2) % STAGES;
                    if (i + 2 >= STAGES) {
                        MBAR_WAIT(EMPTY + 16 * s2, (((i + 2) / 3) - 1) & 1);
                    }
                    issue_stage(s2, i + 2);
                }
            }
            if (ks < 3) {
                load_frags(scur, ks + 1, b ^ 1);
            } else if (i + 1 < CHUNKS) {
                load_frags(s1, 0, b ^ 1);
            }
            #pragma unroll
            for (int mt = 0; mt < 4; mt++)
                #pragma unroll
                for (int nt = 0; nt < 4; nt++)
                    mma16816(acc[mt][nt], af[b][mt], bf[b][nt >> 1] + (nt & 1) * 2);
        }
        // per-thread arrive at END of iteration: each thread's release
        // orders its own ldmatrix reads, with the ks=3 LDSM batch + MMA
        // block of temporal margin before any producer overwrite (the
        // R14 experiment showed an arrive abutting the last LDSM races).
        MBAR_ARRIVE(EMPTY + 16 * scur);
    }

    // epilogue: scale columns, write fp32
    const int g = lane >> 2, qn = lane & 3;
    #pragma unroll
    for (int nt = 0; nt < 4; nt++) {
        const int col = wn * 32 + nt * 8 + qn * 2;
        const float2 s2 = *reinterpret_cast<const float2*>(&g_scale[nbase + col]);
        #pragma unroll
        for (int mt = 0; mt < 4; mt++) {
            const int row0 = mrow + wm * 64 + mt * 16 + g;
            float2 v0 = { acc[mt][nt][0] * s2.x, acc[mt][nt][1] * s2.y };
            float2 v1 = { acc[mt][nt][2] * s2.x, acc[mt][nt][3] * s2.y };
            *reinterpret_cast<float2*>(out + (size_t)row0 * N + nbase + col) = v0;
            *reinterpret_cast<float2*>(out + (size_t)(row0 + 8) * N + nbase + col) = v1;
        }
    }
}

// ---------------------------------------------------------------------------
// Host launch
// ---------------------------------------------------------------------------
typedef CUresult (*PFN_tmEnc)(CUtensorMap*, CUtensorMapDataType, cuuint32_t, void*,
                              const cuuint64_t*, const cuuint64_t*, const cuuint32_t*,
                              const cuuint32_t*, CUtensorMapInterleave, CUtensorMapSwizzle,
                              CUtensorMapL2promotion, CUtensorMapFloatOOBfill);

static void make2d(PFN_tmEnc enc, CUtensorMap* tm, void* ptr, uint64_t rows,
                   uint32_t box_rows) {
    cuuint64_t dims[2] = {(cuuint64_t)K, rows};
    cuuint64_t strides[1] = {(cuuint64_t)K * 2};
    cuuint32_t box[2] = {64, box_rows};     // 64 halves = 128B x box_rows
    cuuint32_t es[2] = {1, 1};
    enc(tm, CU_TENSOR_MAP_DATA_TYPE_BFLOAT16 /* 2-byte elems; layout-only */,
        2, ptr, dims, strides, box, es,
        CU_TENSOR_MAP_INTERLEAVE_NONE, CU_TENSOR_MAP_SWIZZLE_128B,
        CU_TENSOR_MAP_L2_PROMOTION_L2_128B, CU_TENSOR_MAP_FLOAT_OOB_FILL_NONE);
}

extern "C" void kernel_launch(void* const* d_in, const int* in_sizes, int n_in,
                              void* d_out, int out_size) {
    const float* x = (const float*)d_in[0];   // [8192, 4096]
    const float* w = (const float*)d_in[1];   // [4096, 4096]
    float* out = (float*)d_out;               // [8192, 4096]

    void *p_q = nullptr, *p_xh = nullptr;
    cudaGetSymbolAddress(&p_q, g_q);
    cudaGetSymbolAddress(&p_xh, g_xh);

    PFN_tmEnc enc = nullptr;
    cudaDriverEntryPointQueryResult qr;
    cudaGetDriverEntryPoint("cuTensorMapEncodeTiled", (void**)&enc, cudaEnableDefault, &qr);

    CUtensorMap tmA, tmB;
    make2d(enc, &tmA, p_xh, M, 128);
    make2d(enc, &tmB, p_q, N, 64);

    cudaFuncSetAttribute(gemm_kernel, cudaFuncAttributeMaxDynamicSharedMemorySize, SMEM_SIZE);

    const int conv_blocks = (int)(((size_t)M * K / 8) / 256);  // 16384
    prep_kernel<<<N + conv_blocks, 256>>>(w, x);
    gemm_kernel<<<dim3(N / BN, M / BM), 128, SMEM_SIZE>>>(tmA, tmB, out);
}

// round 16
// speedup vs baseline: 1.0103x; 1.0103x over previous
#include <cuda_runtime.h>
#include <cuda.h>
#include <cuda_fp16.h>
#include <cstdint>

// ============================================================================
// TernaryLinear: out[8192,4096] = x[8192,4096] @ (ternary(w)[4096,4096]).T
//
// out = (x @ q^T) * scale[col], q in {-1,0,1} exact in fp16; x -> fp16
// (u=2^-11 => ~3.5e-4 rel err, measured). fp32 accumulate in registers.
//
// R16 = R13 FINAL FREEZE (best passing config: 542.8us, tensor 91.1%).
// Session summary: HMMA plateau ~91% confirmed across 5 sync variants;
// tcgen05.ld blocked by compute_103 PTX target; prep at HBM ceiling.
// Config: 3 CTAs/SM x 128 thr, 128x64 CTA tiles, 64x32 warp tiles, BK=64,
// 3-stage TMA+mbarrier pipeline (FULL count-1+expect_tx, EMPTY count-128
// per-thread end-of-iteration arrives -- the proven-safe placement; the
// R12/R14 experiments showed elected or LDSM-abutting arrives race TMA
// overwrite), rotating TMA duty warp, 2-way phase-staggered full waits,
// cross-chunk ldmatrix prefetch, register frag double-buffering.
// ============================================================================

#define DINLINE __device__ __forceinline__

static constexpr int M = 8192, N = 4096, K = 4096;
static constexpr int BM = 128, BN = 64, BK = 64;
static constexpr int CHUNKS = K / BK;                  // 64
static constexpr int STAGES = 3;
static constexpr int STAGE_BYTES = (BM + BN) * BK * 2; // 24576
static constexpr int SMEM_STAGE0 = 1024;               // barriers live below
static constexpr int SMEM_SIZE = SMEM_STAGE0 + STAGES * STAGE_BYTES; // 74752

// scratch (device globals: allocation-free)
__device__ __half g_q[(size_t)N * K];     // ternary weights, fp16 exact
__device__ __half g_xh[(size_t)M * K];    // x in fp16
__device__ float  g_scale[N];

// ---------------------------------------------------------------------------
// helpers
// ---------------------------------------------------------------------------
DINLINE uint32_t smem_u32(const void* p) {
    uint32_t a;
    asm("{ .reg .u64 t; cvta.to.shared.u64 t, %1; cvt.u32.u64 %0, t; }" : "=r"(a) : "l"(p));
    return a;
}
DINLINE uint32_t elect_one() {
    uint32_t p;
    asm volatile("{ .reg .pred p; elect.sync _|p, 0xFFFFFFFF; selp.b32 %0, 1, 0, p; }" : "=r"(p));
    return p;
}
#define MBAR_INIT(a, c) asm volatile("mbarrier.init.shared.b64 [%0], %1;" :: "r"(a), "r"(c) : "memory")
#define MBAR_ARRIVE(a)  asm volatile("mbarrier.arrive.shared.b64 _, [%0];" :: "r"(a) : "memory")
#define MBAR_EXPECT_TX(a, b) asm volatile("mbarrier.arrive.expect_tx.shared.b64 _, [%0], %1;" :: "r"(a), "r"(b) : "memory")
#define MBAR_WAIT(a, ph) do {                                                     \
    uint32_t _m = (a), _p = (ph), _d;                                             \
    asm volatile("{ .reg .pred p; mbarrier.try_wait.parity.acquire.cta.shared::cta.b64 p, [%1], %2; selp.b32 %0,1,0,p; }" \
        : "=r"(_d) : "r"(_m), "r"(_p) : "memory");                                \
    if (!_d) {                                                                    \
        asm volatile("{ .reg .pred P1; W%=: mbarrier.try_wait.parity.acquire.cta.shared::cta.b64 P1, [%0], %1, 0x989680; @P1 bra.uni D%=; bra.uni W%=; D%=: }" \
            :: "r"(_m), "r"(_p) : "memory");                                      \
    }                                                                             \
} while (0)

#define TMA_LOAD_2D(smem, map, cx, cy, mbar)                                      \
    asm volatile("cp.async.bulk.tensor.2d.shared::cta.global.tile.mbarrier::complete_tx::bytes [%0], [%1, {%2, %3}], [%4];" \
        :: "r"(smem), "l"(map), "r"(cx), "r"(cy), "r"(mbar) : "memory")

DINLINE void ldsm4(uint32_t* r, uint32_t addr) {
    asm volatile("ldmatrix.sync.aligned.m8n8.x4.shared.b16 {%0,%1,%2,%3}, [%4];"
                 : "=r"(r[0]), "=r"(r[1]), "=r"(r[2]), "=r"(r[3]) : "r"(addr));
}
DINLINE void mma16816(float* c, const uint32_t* a, const uint32_t* b) {
    asm volatile(
        "mma.sync.aligned.m16n8k16.row.col.f32.f16.f16.f32 "
        "{%0,%1,%2,%3}, {%4,%5,%6,%7}, {%8,%9}, {%0,%1,%2,%3};"
        : "+f"(c[0]), "+f"(c[1]), "+f"(c[2]), "+f"(c[3])
        : "r"(a[0]), "r"(a[1]), "r"(a[2]), "r"(a[3]), "r"(b[0]), "r"(b[1]));
}

// ---------------------------------------------------------------------------
// Fused prep: blocks [0, N) quantize w rows (one-pass, row in registers);
// blocks [N, N + M*K/2048) convert x to fp16.
// ---------------------------------------------------------------------------
__global__ void __launch_bounds__(256) prep_kernel(const float* __restrict__ w,
                                                   const float* __restrict__ x) {
    if (blockIdx.x < (unsigned)N) {
        const int row = blockIdx.x, tid = threadIdx.x;
        const float4* wr = reinterpret_cast<const float4*>(w + (size_t)row * K);
        float4 v[4];
        float s = 0.f;
        #pragma unroll
        for (int t = 0; t < 4; t++) {
            v[t] = wr[tid + 256 * t];
            s += fabsf(v[t].x) + fabsf(v[t].y) + fabsf(v[t].z) + fabsf(v[t].w);
        }
        for (int o = 16; o; o >>= 1) s += __shfl_xor_sync(~0u, s, o);
        __shared__ float warp_s[8];
        __shared__ float sc;
        if ((tid & 31) == 0) warp_s[tid >> 5] = s;
        __syncthreads();
        if (tid == 0) {
            float t = 0.f;
            for (int i = 0; i < 8; i++) t += warp_s[i];
            float m = t * (1.f / (float)K);
            if (m < 1e-5f) m = 1e-5f;
            sc = m;
            g_scale[row] = m;
        }
        __syncthreads();
        const float inv = 1.f / sc;
        __half2* qr = reinterpret_cast<__half2*>(g_q + (size_t)row * K);
        #pragma unroll
        for (int t = 0; t < 4; t++) {
            float q0 = fminf(fmaxf(rintf(v[t].x * inv), -1.f), 1.f);
            float q1 = fminf(fmaxf(rintf(v[t].y * inv), -1.f), 1.f);
            float q2 = fminf(fmaxf(rintf(v[t].z * inv), -1.f), 1.f);
            float q3 = fminf(fmaxf(rintf(v[t].w * inv), -1.f), 1.f);
            qr[2 * (tid + 256 * t)]     = __floats2half2_rn(q0, q1);
            qr[2 * (tid + 256 * t) + 1] = __floats2half2_rn(q2, q3);
        }
    } else {
        size_t i = (size_t)(blockIdx.x - N) * 256 + threadIdx.x;  // 8 floats each
        const float4* x4 = reinterpret_cast<const float4*>(x);
        float4 a = x4[2 * i], b = x4[2 * i + 1];
        __half2 h0 = __floats2half2_rn(a.x, a.y);
        __half2 h1 = __floats2half2_rn(a.z, a.w);
        __half2 h2 = __floats2half2_rn(b.x, b.y);
        __half2 h3 = __floats2half2_rn(b.z, b.w);
        uint4 o;
        o.x = *reinterpret_cast<uint32_t*>(&h0);
        o.y = *reinterpret_cast<uint32_t*>(&h1);
        o.z = *reinterpret_cast<uint32_t*>(&h2);
        o.w = *reinterpret_cast<uint32_t*>(&h3);
        reinterpret_cast<uint4*>(g_xh)[i] = o;
    }
}

// ---------------------------------------------------------------------------
// GEMM: CTA 128x64, BK=64, 3-stage TMA+mbarrier pipeline, 4 warps (2m x 2n),
// 3 CTAs/SM (3 warps per SMSP). Warp tile 64x32 via mma.sync.m16n8k16,
// register frag double-buffering with cross-chunk prefetch.
// EMPTY: count-128, per-thread arrives at end of iteration (sound ordering).
// ---------------------------------------------------------------------------
__global__ void __launch_bounds__(128, 3) gemm_kernel(
    const __grid_constant__ CUtensorMap tmA,
    const __grid_constant__ CUtensorMap tmB,
    float* __restrict__ out)        // [M,N] fp32
{
    extern __shared__ char smem[];
    const uint32_t sbase = smem_u32(smem);
    const int tid = threadIdx.x, lane = tid & 31, wid = tid >> 5;
    const int wm = wid >> 1, wn = wid & 1;     // warp tile: (wm*64, wn*32)
    const int mrow = blockIdx.y * BM;
    const int nbase = blockIdx.x * BN;
    const unsigned bid = blockIdx.y * gridDim.x + blockIdx.x;
    const int phase = (bid >> 2) & 1;          // differs across (b, b+148)

    // barriers: full[0..2] at sbase+0,16,32 ; empty[0..2] at sbase+48,64,80
    const uint32_t FULL = sbase, EMPTY = sbase + 48;
    const uint32_t STAGE0 = sbase + SMEM_STAGE0;

    if (tid == 0) {
        #pragma unroll
        for (int s = 0; s < 3; s++) {
            MBAR_INIT(FULL + 16 * s, 1);
            MBAR_INIT(EMPTY + 16 * s, 128);    // per-thread arrives
        }
    }
    __syncthreads();

    float acc[4][4][4];
    #pragma unroll
    for (int i = 0; i < 4; i++)
        #pragma unroll
        for (int j = 0; j < 4; j++)
            #pragma unroll
            for (int k = 0; k < 4; k++) acc[i][j][k] = 0.f;

    // ldmatrix lane coords
    const int arow = lane & 15, asel = lane >> 4;
    const int brow = (lane & 7) + ((lane >> 4) << 3), bsel = (lane >> 3) & 1;
    const int axor = arow & 7, bxor = brow & 7;

    // TMA stage issue (caller must be warp-uniform; elected lane only)
    auto issue_stage = [&](int s, int kc) {
        const uint32_t sA = STAGE0 + s * STAGE_BYTES;
        MBAR_EXPECT_TX(FULL + 16 * s, (uint32_t)STAGE_BYTES);
        TMA_LOAD_2D(sA,            &tmA, kc * BK, mrow,  FULL + 16 * s);
        TMA_LOAD_2D(sA + BM * 128, &tmB, kc * BK, nbase, FULL + 16 * s);
    };

    uint32_t af[2][4][4], bf[2][2][4];

    auto load_frags = [&](int s, int ks, int buf) {
        const uint32_t aB = STAGE0 + s * STAGE_BYTES;
        const uint32_t bB = aB + BM * 128;
        #pragma unroll
        for (int mt = 0; mt < 4; mt++) {
            const int row = wm * 64 + mt * 16 + arow;
            ldsm4(af[buf][mt], aB + row * 128 + (((ks * 2 + asel) ^ axor) << 4));
        }
        #pragma unroll
        for (int p = 0; p < 2; p++) {
            const int row = wn * 32 + p * 16 + brow;
            ldsm4(bf[buf][p], bB + row * 128 + (((ks * 2 + bsel) ^ bxor) << 4));
        }
    };

    // prologue: issue chunks 0 and 1; wait chunk 0; prefetch frags(0,0)
    if (wid == 0 && elect_one()) {
        issue_stage(0, 0);
        issue_stage(1, 1);
    }
    MBAR_WAIT(FULL + 0, 0);
    load_frags(0, 0, 0);

    for (int i = 0; i < CHUNKS; i++) {
        const int scur = i % STAGES;
        const int s1 = (i + 1) % STAGES;
        const uint32_t ph1 = ((i + 1) / 3) & 1;

        #pragma unroll
        for (int ks = 0; ks < 4; ks++) {
            const int b = ks & 1;
            if (ks == 1) {
                // odd-phase CTAs: wait for next chunk here (data issued 2
                // chunks ago -> long complete; decorrelates co-CTA stalls)
                if (phase && i + 1 < CHUNKS) {
                    MBAR_WAIT(FULL + 16 * s1, ph1);
                }
                if (i + 2 < CHUNKS && wid == ((i + 2) & 3)) {
                    // rotate TMA-issue duty across warps; WAR-gate on empty
                    if (elect_one()) {
                        const int s2 = (i + 2) % STAGES;
                        if (i + 2 >= STAGES) {
                            MBAR_WAIT(EMPTY + 16 * s2, (((i + 2) / 3) - 1) & 1);
                        }
                        issue_stage(s2, i + 2);
                    }
                }
            }
            if (ks < 3) {
                load_frags(scur, ks + 1, b ^ 1);
            } else if (i + 1 < CHUNKS) {
                if (!phase) MBAR_WAIT(FULL + 16 * s1, ph1);
                load_frags(s1, 0, b ^ 1);
            }
            #pragma unroll
            for (int mt = 0; mt < 4; mt++)
                #pragma unroll
                for (int nt = 0; nt < 4; nt++)
                    mma16816(acc[mt][nt], af[b][mt], bf[b][nt >> 1] + (nt & 1) * 2);
        }
        // per-thread arrive: each thread's release orders ITS OWN ldmatrix
        // participation (last read of scur was issued at ks==2), with the
        // ks=3 LDSM batch + MMA block of temporal margin before producer
        // overwrite (R14 showed an arrive abutting the last LDSM races).
        MBAR_ARRIVE(EMPTY + 16 * scur);
    }

    // epilogue: scale columns, write fp32
    const int g = lane >> 2, qn = lane & 3;
    #pragma unroll
    for (int nt = 0; nt < 4; nt++) {
        const int col = wn * 32 + nt * 8 + qn * 2;
        const float2 s2 = *reinterpret_cast<const float2*>(&g_scale[nbase + col]);
        #pragma unroll
        for (int mt = 0; mt < 4; mt++) {
            const int row0 = mrow + wm * 64 + mt * 16 + g;
            float2 v0 = { acc[mt][nt][0] * s2.x, acc[mt][nt][1] * s2.y };
            float2 v1 = { acc[mt][nt][2] * s2.x, acc[mt][nt][3] * s2.y };
            *reinterpret_cast<float2*>(out + (size_t)row0 * N + nbase + col) = v0;
            *reinterpret_cast<float2*>(out + (size_t)(row0 + 8) * N + nbase + col) = v1;
        }
    }
}

// ---------------------------------------------------------------------------
// Host launch
// ---------------------------------------------------------------------------
typedef CUresult (*PFN_tmEnc)(CUtensorMap*, CUtensorMapDataType, cuuint32_t, void*,
                              const cuuint64_t*, const cuuint64_t*, const cuuint32_t*,
                              const cuuint32_t*, CUtensorMapInterleave, CUtensorMapSwizzle,
                              CUtensorMapL2promotion, CUtensorMapFloatOOBfill);

static void make2d(PFN_tmEnc enc, CUtensorMap* tm, void* ptr, uint64_t rows,
                   uint32_t box_rows) {
    cuuint64_t dims[2] = {(cuuint64_t)K, rows};
    cuuint64_t strides[1] = {(cuuint64_t)K * 2};
    cuuint32_t box[2] = {64, box_rows};     // 64 halves = 128B x box_rows
    cuuint32_t es[2] = {1, 1};
    enc(tm, CU_TENSOR_MAP_DATA_TYPE_BFLOAT16 /* 2-byte elems; layout-only */,
        2, ptr, dims, strides, box, es,
        CU_TENSOR_MAP_INTERLEAVE_NONE, CU_TENSOR_MAP_SWIZZLE_128B,
        CU_TENSOR_MAP_L2_PROMOTION_L2_128B, CU_TENSOR_MAP_FLOAT_OOB_FILL_NONE);
}

extern "C" void kernel_launch(void* const* d_in, const int* in_sizes, int n_in,
                              void* d_out, int out_size) {
    const float* x = (const float*)d_in[0];   // [8192, 4096]
    const float* w = (const float*)d_in[1];   // [4096, 4096]
    float* out = (float*)d_out;               // [8192, 4096]

    void *p_q = nullptr, *p_xh = nullptr;
    cudaGetSymbolAddress(&p_q, g_q);
    cudaGetSymbolAddress(&p_xh, g_xh);

    PFN_tmEnc enc = nullptr;
    cudaDriverEntryPointQueryResult qr;
    cudaGetDriverEntryPoint("cuTensorMapEncodeTiled", (void**)&enc, cudaEnableDefault, &qr);

    CUtensorMap tmA, tmB;
    make2d(enc, &tmA, p_xh, M, 128);
    make2d(enc, &tmB, p_q, N, 64);

    cudaFuncSetAttribute(gemm_kernel, cudaFuncAttributeMaxDynamicSharedMemorySize, SMEM_SIZE);

    const int conv_blocks = (int)(((size_t)M * K / 8) / 256);  // 16384
    prep_kernel<<<N + conv_blocks, 256>>>(w, x);
    gemm_kernel<<<dim3(N / BN, M / BM), 128, SMEM_SIZE>>>(tmA, tmB, out);
}

// round 17
// speedup vs baseline: 1.0121x; 1.0018x over previous
#include <cuda_runtime.h>
#include <cuda.h>
#include <cuda_fp16.h>
#include <cstdint>

// ============================================================================
// TernaryLinear: out[8192,4096] = x[8192,4096] @ (ternary(w)[4096,4096]).T
//
// out = (x @ q^T) * scale[col], q in {-1,0,1} exact in fp16; x -> fp16
// (u=2^-11 => ~3.5e-4 rel err, measured). fp32 accumulate in registers.
//
// R17 = R16 (best: 542.2us, tensor 91.0%) + L2-protection epilogue:
//  1. Output stores use st.global.cs (evict-first): the 128MB write-once
//     output stream no longer displaces the live A/B working set in L2
//     (B is 32MB, re-read across ~9 waves; L2 was 46.5% busy).
//  2. Per-warp g_scale values prefetched into registers BEFORE the main
//     loop -- epilogue stores no longer serialize behind a cold LDG.
// Everything else identical to the proven config: 3 CTAs/SM x 128 thr,
// 128x64 CTA tiles, 64x32 warp tiles, BK=64, 3-stage TMA+mbarrier
// pipeline (FULL count-1+expect_tx; EMPTY count-128 per-thread
// end-of-iteration arrives -- R12/R14 showed elected or LDSM-abutting
// arrives race TMA overwrite), rotating TMA duty warp, 2-way phase-
// staggered full waits, cross-chunk ldmatrix prefetch, frag double-buffer.
// ============================================================================

#define DINLINE __device__ __forceinline__

static constexpr int M = 8192, N = 4096, K = 4096;
static constexpr int BM = 128, BN = 64, BK = 64;
static constexpr int CHUNKS = K / BK;                  // 64
static constexpr int STAGES = 3;
static constexpr int STAGE_BYTES = (BM + BN) * BK * 2; // 24576
static constexpr int SMEM_STAGE0 = 1024;               // barriers live below
static constexpr int SMEM_SIZE = SMEM_STAGE0 + STAGES * STAGE_BYTES; // 74752

// scratch (device globals: allocation-free)
__device__ __half g_q[(size_t)N * K];     // ternary weights, fp16 exact
__device__ __half g_xh[(size_t)M * K];    // x in fp16
__device__ float  g_scale[N];

// ---------------------------------------------------------------------------
// helpers
// ---------------------------------------------------------------------------
DINLINE uint32_t smem_u32(const void* p) {
    uint32_t a;
    asm("{ .reg .u64 t; cvta.to.shared.u64 t, %1; cvt.u32.u64 %0, t; }" : "=r"(a) : "l"(p));
    return a;
}
DINLINE uint32_t elect_one() {
    uint32_t p;
    asm volatile("{ .reg .pred p; elect.sync _|p, 0xFFFFFFFF; selp.b32 %0, 1, 0, p; }" : "=r"(p));
    return p;
}
#define MBAR_INIT(a, c) asm volatile("mbarrier.init.shared.b64 [%0], %1;" :: "r"(a), "r"(c) : "memory")
#define MBAR_ARRIVE(a)  asm volatile("mbarrier.arrive.shared.b64 _, [%0];" :: "r"(a) : "memory")
#define MBAR_EXPECT_TX(a, b) asm volatile("mbarrier.arrive.expect_tx.shared.b64 _, [%0], %1;" :: "r"(a), "r"(b) : "memory")
#define MBAR_WAIT(a, ph) do {                                                     \
    uint32_t _m = (a), _p = (ph), _d;                                             \
    asm volatile("{ .reg .pred p; mbarrier.try_wait.parity.acquire.cta.shared::cta.b64 p, [%1], %2; selp.b32 %0,1,0,p; }" \
        : "=r"(_d) : "r"(_m), "r"(_p) : "memory");                                \
    if (!_d) {                                                                    \
        asm volatile("{ .reg .pred P1; W%=: mbarrier.try_wait.parity.acquire.cta.shared::cta.b64 P1, [%0], %1, 0x989680; @P1 bra.uni D%=; bra.uni W%=; D%=: }" \
            :: "r"(_m), "r"(_p) : "memory");                                      \
    }                                                                             \
} while (0)

#define TMA_LOAD_2D(smem, map, cx, cy, mbar)                                      \
    asm volatile("cp.async.bulk.tensor.2d.shared::cta.global.tile.mbarrier::complete_tx::bytes [%0], [%1, {%2, %3}], [%4];" \
        :: "r"(smem), "l"(map), "r"(cx), "r"(cy), "r"(mbar) : "memory")

DINLINE void ldsm4(uint32_t* r, uint32_t addr) {
    asm volatile("ldmatrix.sync.aligned.m8n8.x4.shared.b16 {%0,%1,%2,%3}, [%4];"
                 : "=r"(r[0]), "=r"(r[1]), "=r"(r[2]), "=r"(r[3]) : "r"(addr));
}
DINLINE void mma16816(float* c, const uint32_t* a, const uint32_t* b) {
    asm volatile(
        "mma.sync.aligned.m16n8k16.row.col.f32.f16.f16.f32 "
        "{%0,%1,%2,%3}, {%4,%5,%6,%7}, {%8,%9}, {%0,%1,%2,%3};"
        : "+f"(c[0]), "+f"(c[1]), "+f"(c[2]), "+f"(c[3])
        : "r"(a[0]), "r"(a[1]), "r"(a[2]), "r"(a[3]), "r"(b[0]), "r"(b[1]));
}
// streaming (evict-first) output store: keeps write-once data out of the
// live L2 working set that TMA A/B reads depend on.
DINLINE void stg_cs_v2(float* p, float x, float y) {
    asm volatile("st.global.cs.v2.f32 [%0], {%1, %2};" :: "l"(p), "f"(x), "f"(y) : "memory");
}

// ---------------------------------------------------------------------------
// Fused prep: blocks [0, N) quantize w rows (one-pass, row in registers);
// blocks [N, N + M*K/2048) convert x to fp16.
// ---------------------------------------------------------------------------
__global__ void __launch_bounds__(256) prep_kernel(const float* __restrict__ w,
                                                   const float* __restrict__ x) {
    if (blockIdx.x < (unsigned)N) {
        const int row = blockIdx.x, tid = threadIdx.x;
        const float4* wr = reinterpret_cast<const float4*>(w + (size_t)row * K);
        float4 v[4];
        float s = 0.f;
        #pragma unroll
        for (int t = 0; t < 4; t++) {
            v[t] = wr[tid + 256 * t];
            s += fabsf(v[t].x) + fabsf(v[t].y) + fabsf(v[t].z) + fabsf(v[t].w);
        }
        for (int o = 16; o; o >>= 1) s += __shfl_xor_sync(~0u, s, o);
        __shared__ float warp_s[8];
        __shared__ float sc;
        if ((tid & 31) == 0) warp_s[tid >> 5] = s;
        __syncthreads();
        if (tid == 0) {
            float t = 0.f;
            for (int i = 0; i < 8; i++) t += warp_s[i];
            float m = t * (1.f / (float)K);
            if (m < 1e-5f) m = 1e-5f;
            sc = m;
            g_scale[row] = m;
        }
        __syncthreads();
        const float inv = 1.f / sc;
        __half2* qr = reinterpret_cast<__half2*>(g_q + (size_t)row * K);
        #pragma unroll
        for (int t = 0; t < 4; t++) {
            float q0 = fminf(fmaxf(rintf(v[t].x * inv), -1.f), 1.f);
            float q1 = fminf(fmaxf(rintf(v[t].y * inv), -1.f), 1.f);
            float q2 = fminf(fmaxf(rintf(v[t].z * inv), -1.f), 1.f);
            float q3 = fminf(fmaxf(rintf(v[t].w * inv), -1.f), 1.f);
            qr[2 * (tid + 256 * t)]     = __floats2half2_rn(q0, q1);
            qr[2 * (tid + 256 * t) + 1] = __floats2half2_rn(q2, q3);
        }
    } else {
        size_t i = (size_t)(blockIdx.x - N) * 256 + threadIdx.x;  // 8 floats each
        const float4* x4 = reinterpret_cast<const float4*>(x);
        float4 a = x4[2 * i], b = x4[2 * i + 1];
        __half2 h0 = __floats2half2_rn(a.x, a.y);
        __half2 h1 = __floats2half2_rn(a.z, a.w);
        __half2 h2 = __floats2half2_rn(b.x, b.y);
        __half2 h3 = __floats2half2_rn(b.z, b.w);
        uint4 o;
        o.x = *reinterpret_cast<uint32_t*>(&h0);
        o.y = *reinterpret_cast<uint32_t*>(&h1);
        o.z = *reinterpret_cast<uint32_t*>(&h2);
        o.w = *reinterpret_cast<uint32_t*>(&h3);
        reinterpret_cast<uint4*>(g_xh)[i] = o;
    }
}

// ---------------------------------------------------------------------------
// GEMM: CTA 128x64, BK=64, 3-stage TMA+mbarrier pipeline, 4 warps (2m x 2n),
// 3 CTAs/SM (3 warps per SMSP). Warp tile 64x32 via mma.sync.m16n8k16,
// register frag double-buffering with cross-chunk prefetch.
// EMPTY: count-128, per-thread arrives at end of iteration (sound ordering).
// Output via st.global.cs; scales preloaded before the main loop.
// ---------------------------------------------------------------------------
__global__ void __launch_bounds__(128, 3) gemm_kernel(
    const __grid_constant__ CUtensorMap tmA,
    const __grid_constant__ CUtensorMap tmB,
    float* __restrict__ out)        // [M,N] fp32
{
    extern __shared__ char smem[];
    const uint32_t sbase = smem_u32(smem);
    const int tid = threadIdx.x, lane = tid & 31, wid = tid >> 5;
    const int wm = wid >> 1, wn = wid & 1;     // warp tile: (wm*64, wn*32)
    const int mrow = blockIdx.y * BM;
    const int nbase = blockIdx.x * BN;
    const unsigned bid = blockIdx.y * gridDim.x + blockIdx.x;
    const int phase = (bid >> 2) & 1;          // differs across (b, b+148)

    // barriers: full[0..2] at sbase+0,16,32 ; empty[0..2] at sbase+48,64,80
    const uint32_t FULL = sbase, EMPTY = sbase + 48;
    const uint32_t STAGE0 = sbase + SMEM_STAGE0;

    if (tid == 0) {
        #pragma unroll
        for (int s = 0; s < 3; s++) {
            MBAR_INIT(FULL + 16 * s, 1);
            MBAR_INIT(EMPTY + 16 * s, 128);    // per-thread arrives
        }
    }
    __syncthreads();

    float acc[4][4][4];
    #pragma unroll
    for (int i = 0; i < 4; i++)
        #pragma unroll
        for (int j = 0; j < 4; j++)
            #pragma unroll
            for (int k = 0; k < 4; k++) acc[i][j][k] = 0.f;

    // preload this thread's epilogue scales (4 float2 pairs) before the loop
    const int qn = lane & 3;
    float2 sc[4];
    #pragma unroll
    for (int nt = 0; nt < 4; nt++)
        sc[nt] = *reinterpret_cast<const float2*>(&g_scale[nbase + wn * 32 + nt * 8 + qn * 2]);

    // ldmatrix lane coords
    const int arow = lane & 15, asel = lane >> 4;
    const int brow = (lane & 7) + ((lane >> 4) << 3), bsel = (lane >> 3) & 1;
    const int axor = arow & 7, bxor = brow & 7;

    // TMA stage issue (caller must be warp-uniform; elected lane only)
    auto issue_stage = [&](int s, int kc) {
        const uint32_t sA = STAGE0 + s * STAGE_BYTES;
        MBAR_EXPECT_TX(FULL + 16 * s, (uint32_t)STAGE_BYTES);
        TMA_LOAD_2D(sA,            &tmA, kc * BK, mrow,  FULL + 16 * s);
        TMA_LOAD_2D(sA + BM * 128, &tmB, kc * BK, nbase, FULL + 16 * s);
    };

    uint32_t af[2][4][4], bf[2][2][4];

    auto load_frags = [&](int s, int ks, int buf) {
        const uint32_t aB = STAGE0 + s * STAGE_BYTES;
        const uint32_t bB = aB + BM * 128;
        #pragma unroll
        for (int mt = 0; mt < 4; mt++) {
            const int row = wm * 64 + mt * 16 + arow;
            ldsm4(af[buf][mt], aB + row * 128 + (((ks * 2 + asel) ^ axor) << 4));
        }
        #pragma unroll
        for (int p = 0; p < 2; p++) {
            const int row = wn * 32 + p * 16 + brow;
            ldsm4(bf[buf][p], bB + row * 128 + (((ks * 2 + bsel) ^ bxor) << 4));
        }
    };

    // prologue: issue chunks 0 and 1; wait chunk 0; prefetch frags(0,0)
    if (wid == 0 && elect_one()) {
        issue_stage(0, 0);
        issue_stage(1, 1);
    }
    MBAR_WAIT(FULL + 0, 0);
    load_frags(0, 0, 0);

    for (int i = 0; i < CHUNKS; i++) {
        const int scur = i % STAGES;
        const int s1 = (i + 1) % STAGES;
        const uint32_t ph1 = ((i + 1) / 3) & 1;

        #pragma unroll
        for (int ks = 0; ks < 4; ks++) {
            const int b = ks & 1;
            if (ks == 1) {
                // odd-phase CTAs: wait for next chunk here (data issued 2
                // chunks ago -> long complete; decorrelates co-CTA stalls)
                if (phase && i + 1 < CHUNKS) {
                    MBAR_WAIT(FULL + 16 * s1, ph1);
                }
                if (i + 2 < CHUNKS && wid == ((i + 2) & 3)) {
                    // rotate TMA-issue duty across warps; WAR-gate on empty
                    if (elect_one()) {
                        const int s2 = (i + 2) % STAGES;
                        if (i + 2 >= STAGES) {
                            MBAR_WAIT(EMPTY + 16 * s2, (((i + 2) / 3) - 1) & 1);
                        }
                        issue_stage(s2, i + 2);
                    }
                }
            }
            if (ks < 3) {
                load_frags(scur, ks + 1, b ^ 1);
            } else if (i + 1 < CHUNKS) {
                if (!phase) MBAR_WAIT(FULL + 16 * s1, ph1);
                load_frags(s1, 0, b ^ 1);
            }
            #pragma unroll
            for (int mt = 0; mt < 4; mt++)
                #pragma unroll
                for (int nt = 0; nt < 4; nt++)
                    mma16816(acc[mt][nt], af[b][mt], bf[b][nt >> 1] + (nt & 1) * 2);
        }
        // per-thread arrive: each thread's release orders ITS OWN ldmatrix
        // participation (last read of scur was issued at ks==2), with the
        // ks=3 LDSM batch + MMA block of temporal margin before producer
        // overwrite (R14 showed an arrive abutting the last LDSM races).
        MBAR_ARRIVE(EMPTY + 16 * scur);
    }

    // epilogue: scale columns, write fp32 via streaming stores
    const int g = lane >> 2;
    #pragma unroll
    for (int nt = 0; nt < 4; nt++) {
        const int col = wn * 32 + nt * 8 + qn * 2;
        #pragma unroll
        for (int mt = 0; mt < 4; mt++) {
            const int row0 = mrow + wm * 64 + mt * 16 + g;
            stg_cs_v2(out + (size_t)row0 * N + nbase + col,
                      acc[mt][nt][0] * sc[nt].x, acc[mt][nt][1] * sc[nt].y);
            stg_cs_v2(out + (size_t)(row0 + 8) * N + nbase + col,
                      acc[mt][nt][2] * sc[nt].x, acc[mt][nt][3] * sc[nt].y);
        }
    }
}

// ---------------------------------------------------------------------------
// Host launch
// ---------------------------------------------------------------------------
typedef CUresult (*PFN_tmEnc)(CUtensorMap*, CUtensorMapDataType, cuuint32_t, void*,
                              const cuuint64_t*, const cuuint64_t*, const cuuint32_t*,
                              const cuuint32_t*, CUtensorMapInterleave, CUtensorMapSwizzle,
                              CUtensorMapL2promotion, CUtensorMapFloatOOBfill);

static void make2d(PFN_tmEnc enc, CUtensorMap* tm, void* ptr, uint64_t rows,
                   uint32_t box_rows) {
    cuuint64_t dims[2] = {(cuuint64_t)K, rows};
    cuuint64_t strides[1] = {(cuuint64_t)K * 2};
    cuuint32_t box[2] = {64, box_rows};     // 64 halves = 128B x box_rows
    cuuint32_t es[2] = {1, 1};
    enc(tm, CU_TENSOR_MAP_DATA_TYPE_BFLOAT16 /* 2-byte elems; layout-only */,
        2, ptr, dims, strides, box, es,
        CU_TENSOR_MAP_INTERLEAVE_NONE, CU_TENSOR_MAP_SWIZZLE_128B,
        CU_TENSOR_MAP_L2_PROMOTION_L2_128B, CU_TENSOR_MAP_FLOAT_OOB_FILL_NONE);
}

extern "C" void kernel_launch(void* const* d_in, const int* in_sizes, int n_in,
                              void* d_out, int out_size) {
    const float* x = (const float*)d_in[0];   // [8192, 4096]
    const float* w = (const float*)d_in[1];   // [4096, 4096]
    float* out = (float*)d_out;               // [8192, 4096]

    void *p_q = nullptr, *p_xh = nullptr;
    cudaGetSymbolAddress(&p_q, g_q);
    cudaGetSymbolAddress(&p_xh, g_xh);

    PFN_tmEnc enc = nullptr;
    cudaDriverEntryPointQueryResult qr;
    cudaGetDriverEntryPoint("cuTensorMapEncodeTiled", (void**)&enc, cudaEnableDefault, &qr);

    CUtensorMap tmA, tmB;
    make2d(enc, &tmA, p_xh, M, 128);
    make2d(enc, &tmB, p_q, N, 64);

    cudaFuncSetAttribute(gemm_kernel, cudaFuncAttributeMaxDynamicSharedMemorySize, SMEM_SIZE);

    const int conv_blocks = (int)(((size_t)M * K / 8) / 256);  // 16384
    prep_kernel<<<N + conv_blocks, 256>>>(w, x);
    gemm_kernel<<<dim3(N / BN, M / BM), 128, SMEM_SIZE>>>(tmA, tmB, out);
}